// round 3
// baseline (speedup 1.0000x reference)
#include <cuda_runtime.h>
#include <math.h>

#define NROWS 8192
#define DIMK  512
#define KTOP  10
#define SCALE 0.04419417382415922f   // 512^-0.5

// Scratch embeddings (bss, no allocation)
__device__ float g_eh[NROWS * DIMK];   // pre-scaled by SCALE
__device__ float g_et[NROWS * DIMK];

// Packed fp32x2 FMA (sm_103a): c += a * b on both lanes
__device__ __forceinline__ void ffma2(float2& c, float2 a, float2 b) {
    asm("fma.rn.f32x2 %0, %1, %2, %0;"
        : "+l"(*reinterpret_cast<unsigned long long*>(&c))
        : "l"(*reinterpret_cast<unsigned long long*>(&a)),
          "l"(*reinterpret_cast<unsigned long long*>(&b)));
}

// ---------------------------------------------------------------------------
// Kernel A: E = X @ W^T + b   (E[i][j] = sum_k X[i,k]*W[j,k] + b[j]) * sc
// Tile 64x64, BK=32, 256 threads, 16 outputs/thread (8 rows as 4 pairs x 2 cols)
// ---------------------------------------------------------------------------
__global__ void embed_kernel(const float* __restrict__ X,
                             const float* __restrict__ W0, const float* __restrict__ b0,
                             const float* __restrict__ W1, const float* __restrict__ b1)
{
    const int z = blockIdx.z;
    const float* W    = z ? W1 : W0;
    const float* bias = z ? b1 : b0;
    float* out        = z ? g_et : g_eh;
    const float sc    = z ? 1.0f : SCALE;

    __shared__ float Xs[32][64];   // [k][row]
    __shared__ float Ws[32][64];   // [k][col]

    const int tid = threadIdx.x;
    const int rb = blockIdx.y * 64;
    const int cb = blockIdx.x * 64;
    const int ty = tid >> 5;       // 0..7  (8 rows each)
    const int tx = tid & 31;       // cols 2*tx, 2*tx+1

    float2 acc[4][2];
    #pragma unroll
    for (int i = 0; i < 4; i++) { acc[i][0] = make_float2(0.f, 0.f); acc[i][1] = make_float2(0.f, 0.f); }

    const int lr = tid & 63;            // row/col within tile for loading
    const int lk = (tid >> 6) * 8;      // 8 consecutive k per thread

    for (int kc = 0; kc < DIMK; kc += 32) {
        __syncthreads();
        #pragma unroll
        for (int j = 0; j < 8; j += 4) {
            float4 xv = *(const float4*)(X + (size_t)(rb + lr) * DIMK + kc + lk + j);
            Xs[lk + j + 0][lr] = xv.x; Xs[lk + j + 1][lr] = xv.y;
            Xs[lk + j + 2][lr] = xv.z; Xs[lk + j + 3][lr] = xv.w;
            float4 wv = *(const float4*)(W + (size_t)(cb + lr) * DIMK + kc + lk + j);
            Ws[lk + j + 0][lr] = wv.x; Ws[lk + j + 1][lr] = wv.y;
            Ws[lk + j + 2][lr] = wv.z; Ws[lk + j + 3][lr] = wv.w;
        }
        __syncthreads();
        #pragma unroll
        for (int k = 0; k < 32; k++) {
            float4 a0 = *(const float4*)&Xs[k][ty * 8];
            float4 a1 = *(const float4*)&Xs[k][ty * 8 + 4];
            float2 wb = *(const float2*)&Ws[k][2 * tx];
            float2 ap0 = make_float2(a0.x, a0.y);
            float2 ap1 = make_float2(a0.z, a0.w);
            float2 ap2 = make_float2(a1.x, a1.y);
            float2 ap3 = make_float2(a1.z, a1.w);
            float2 bb0 = make_float2(wb.x, wb.x);
            float2 bb1 = make_float2(wb.y, wb.y);
            ffma2(acc[0][0], ap0, bb0); ffma2(acc[1][0], ap1, bb0);
            ffma2(acc[2][0], ap2, bb0); ffma2(acc[3][0], ap3, bb0);
            ffma2(acc[0][1], ap0, bb1); ffma2(acc[1][1], ap1, bb1);
            ffma2(acc[2][1], ap2, bb1); ffma2(acc[3][1], ap3, bb1);
        }
    }

    #pragma unroll
    for (int rp = 0; rp < 4; rp++) {
        #pragma unroll
        for (int cc = 0; cc < 2; cc++) {
            int col = cb + 2 * tx + cc;
            float bv = bias[col];
            int r0 = rb + ty * 8 + 2 * rp;
            out[(size_t)r0 * DIMK + col]       = (acc[rp][cc].x + bv) * sc;
            out[(size_t)(r0 + 1) * DIMK + col] = (acc[rp][cc].y + bv) * sc;
        }
    }
}

// ---------------------------------------------------------------------------
// Kernel B: logits = e_h @ e_t^T (already scaled), fused top-10 + softmax +
// edge emission. One block per 64-row stripe; A stripe (64x512) resident in
// smem; B streamed in 64x128 column tiles, double-buffered BK=64 chunks.
// ---------------------------------------------------------------------------
#define SMEM_B_FLOATS (DIMK * 64 + 2 * 64 * 128 + 64 * KTOP)          // As + Bs + topv
#define SMEM_B_BYTES  (SMEM_B_FLOATS * 4 + 64 * KTOP * 4)             // + topi

__global__ void __launch_bounds__(256, 1)
logits_topk_kernel(float* __restrict__ src_p, float* __restrict__ dst_p,
                   float* __restrict__ w_p)
{
    extern __shared__ float sm[];
    float* As   = sm;                                  // [512][64] k-major
    float* Bs   = sm + DIMK * 64;                      // 2 x [64][128] k-major
    float* topv = Bs + 2 * 64 * 128;                   // [64][10]
    int*   topi = (int*)(topv + 64 * KTOP);            // [64][10]

    const int tid = threadIdx.x;
    const int rb  = blockIdx.x * 64;
    const int ty  = tid >> 5;       // 0..7 -> rows ty*8 .. ty*8+7
    const int tx  = tid & 31;       // cols 4*tx .. 4*tx+3

    // init top-k
    for (int i = tid; i < 64 * KTOP; i += 256) {
        topv[i] = -INFINITY; topi[i] = 0;
    }

    // load A stripe: As[k][r], 64 rows x 512 k
    {
        const int lr = tid & 63;
        const int kb = (tid >> 6) * 128;
        const float* srcp = g_eh + (size_t)(rb + lr) * DIMK + kb;
        #pragma unroll 4
        for (int kk = 0; kk < 128; kk += 4) {
            float4 v = *(const float4*)(srcp + kk);
            As[(kb + kk + 0) * 64 + lr] = v.x;
            As[(kb + kk + 1) * 64 + lr] = v.y;
            As[(kb + kk + 2) * 64 + lr] = v.z;
            As[(kb + kk + 3) * 64 + lr] = v.w;
        }
    }
    __syncthreads();

    const int bc  = tid & 127;          // column within tile for B loads
    const int bkh = (tid >> 7) * 32;    // k-half within chunk

    for (int ct = 0; ct < NROWS / 128; ct++) {
        const int cbase = ct * 128;
        const float* bsrc = g_et + (size_t)(cbase + bc) * DIMK + bkh;

        float2 acc[4][4];
        #pragma unroll
        for (int i = 0; i < 4; i++)
            #pragma unroll
            for (int j = 0; j < 4; j++) acc[i][j] = make_float2(0.f, 0.f);

        // prefetch + stage chunk 0 into buffer 0
        float4 pre[8];
        #pragma unroll
        for (int j = 0; j < 8; j++) pre[j] = *(const float4*)(bsrc + 4 * j);
        #pragma unroll
        for (int j = 0; j < 8; j++) {
            int kl = bkh + 4 * j;
            Bs[(kl + 0) * 128 + bc] = pre[j].x;
            Bs[(kl + 1) * 128 + bc] = pre[j].y;
            Bs[(kl + 2) * 128 + bc] = pre[j].z;
            Bs[(kl + 3) * 128 + bc] = pre[j].w;
        }

        for (int kc = 0; kc < 8; kc++) {
            __syncthreads();     // buffer(kc&1) ready; prior reads of other buf done
            if (kc < 7) {
                const float* ns = bsrc + (kc + 1) * 64;
                #pragma unroll
                for (int j = 0; j < 8; j++) pre[j] = *(const float4*)(ns + 4 * j);
            }
            const float* Bcur = Bs + (kc & 1) * 8192;
            const float* Acur = As + (kc * 64) * 64 + ty * 8;
            #pragma unroll 8
            for (int k = 0; k < 64; k++) {
                float4 a0 = *(const float4*)(Acur + k * 64);
                float4 a1 = *(const float4*)(Acur + k * 64 + 4);
                float4 b  = *(const float4*)(Bcur + k * 128 + tx * 4);
                float2 ap0 = make_float2(a0.x, a0.y);
                float2 ap1 = make_float2(a0.z, a0.w);
                float2 ap2 = make_float2(a1.x, a1.y);
                float2 ap3 = make_float2(a1.z, a1.w);
                float2 bb;
                bb = make_float2(b.x, b.x);
                ffma2(acc[0][0], ap0, bb); ffma2(acc[1][0], ap1, bb);
                ffma2(acc[2][0], ap2, bb); ffma2(acc[3][0], ap3, bb);
                bb = make_float2(b.y, b.y);
                ffma2(acc[0][1], ap0, bb); ffma2(acc[1][1], ap1, bb);
                ffma2(acc[2][1], ap2, bb); ffma2(acc[3][1], ap3, bb);
                bb = make_float2(b.z, b.z);
                ffma2(acc[0][2], ap0, bb); ffma2(acc[1][2], ap1, bb);
                ffma2(acc[2][2], ap2, bb); ffma2(acc[3][2], ap3, bb);
                bb = make_float2(b.w, b.w);
                ffma2(acc[0][3], ap0, bb); ffma2(acc[1][3], ap1, bb);
                ffma2(acc[2][3], ap2, bb); ffma2(acc[3][3], ap3, bb);
            }
            if (kc < 7) {
                float* Bn = Bs + ((kc + 1) & 1) * 8192;
                #pragma unroll
                for (int j = 0; j < 8; j++) {
                    int kl = bkh + 4 * j;
                    Bn[(kl + 0) * 128 + bc] = pre[j].x;
                    Bn[(kl + 1) * 128 + bc] = pre[j].y;
                    Bn[(kl + 2) * 128 + bc] = pre[j].z;
                    Bn[(kl + 3) * 128 + bc] = pre[j].w;
                }
            }
        }
        __syncthreads();   // all reads of B buffers done before staging reuse

        // stage 64x128 logits tile into Bs region with stride 129 (conflict-free scan)
        {
            const int r0 = ty * 8;
            #pragma unroll
            for (int rp = 0; rp < 4; rp++) {
                #pragma unroll
                for (int cc = 0; cc < 4; cc++) {
                    Bs[(r0 + 2 * rp) * 129 + tx * 4 + cc]     = acc[rp][cc].x;
                    Bs[(r0 + 2 * rp + 1) * 129 + tx * 4 + cc] = acc[rp][cc].y;
                }
            }
        }
        __syncthreads();

        // one thread per row: adaptive-threshold insertion into sorted top-10
        if (tid < 64) {
            const int r = tid;
            float* tv = topv + r * KTOP;
            int*   ti = topi + r * KTOP;
            const float* crow = Bs + r * 129;
            float kv = tv[KTOP - 1];
            for (int c = 0; c < 128; c++) {
                float v = crow[c];
                if (v > kv) {                     // strict > : earlier index wins ties (lax.top_k)
                    int j = KTOP - 1;
                    while (j > 0 && v > tv[j - 1]) {
                        tv[j] = tv[j - 1]; ti[j] = ti[j - 1]; j--;
                    }
                    tv[j] = v; ti[j] = cbase + c;
                    kv = tv[KTOP - 1];
                }
            }
        }
        __syncthreads();
    }

    // softmax + edge emission
    if (tid < 64) {
        const int r = tid, gr = rb + tid;
        float* tv = topv + r * KTOP;
        int*   ti = topi + r * KTOP;
        float m = tv[0];
        float e[KTOP]; float s = 0.f;
        #pragma unroll
        for (int j = 0; j < KTOP; j++) { e[j] = expf(tv[j] - m); s += e[j]; }
        #pragma unroll
        for (int j = 0; j < KTOP; j++) {
            int o = gr * KTOP + j;
            if (src_p) src_p[o] = (float)gr;
            if (dst_p) dst_p[o] = (float)ti[j];
            if (w_p)   w_p[o]   = e[j] / s;
        }
    }
}

// ---------------------------------------------------------------------------
extern "C" void kernel_launch(void* const* d_in, const int* in_sizes, int n_in,
                              void* d_out, int out_size)
{
    const float* X  = (const float*)d_in[0];
    const float* Wh = (const float*)d_in[1];
    const float* bh = (const float*)d_in[2];
    const float* Wt = (const float*)d_in[3];
    const float* bt = (const float*)d_in[4];

    cudaFuncSetAttribute(logits_topk_kernel,
                         cudaFuncAttributeMaxDynamicSharedMemorySize, SMEM_B_BYTES);

    embed_kernel<<<dim3(DIMK / 64, NROWS / 64, 2), 256>>>(X, Wh, bh, Wt, bt);

    const int NK = NROWS * KTOP;   // 81920
    float* out = (float*)d_out;
    float *sp = nullptr, *dp = nullptr, *wp = nullptr;
    if (out_size >= 3 * NK)      { sp = out; dp = out + NK; wp = out + 2 * NK; }
    else if (out_size == 2 * NK) { sp = out; dp = out + NK; }
    else                         { wp = out; }

    logits_topk_kernel<<<NROWS / 64, 256, SMEM_B_BYTES>>>(sp, dp, wp);
}

// round 4
// speedup vs baseline: 1.0236x; 1.0236x over previous
#include <cuda_runtime.h>
#include <math.h>

#define NROWS 8192
#define DIMK  512
#define KTOP  10
#define SCALE 0.04419417382415922f   // 512^-0.5

// Scratch embeddings (bss, no allocation)
__device__ float g_eh[NROWS * DIMK];   // pre-scaled by SCALE
__device__ float g_et[NROWS * DIMK];

// Packed fp32x2 FMA (sm_103a): c += a * b on both lanes
__device__ __forceinline__ void ffma2(float2& c, float2 a, float2 b) {
    asm("fma.rn.f32x2 %0, %1, %2, %0;"
        : "+l"(*reinterpret_cast<unsigned long long*>(&c))
        : "l"(*reinterpret_cast<unsigned long long*>(&a)),
          "l"(*reinterpret_cast<unsigned long long*>(&b)));
}

// ---------------------------------------------------------------------------
// Kernel A: E = (X @ W^T + b) * sc   (unchanged from R2; ~10% of runtime)
// ---------------------------------------------------------------------------
__global__ void embed_kernel(const float* __restrict__ X,
                             const float* __restrict__ W0, const float* __restrict__ b0,
                             const float* __restrict__ W1, const float* __restrict__ b1)
{
    const int z = blockIdx.z;
    const float* W    = z ? W1 : W0;
    const float* bias = z ? b1 : b0;
    float* out        = z ? g_et : g_eh;
    const float sc    = z ? 1.0f : SCALE;

    __shared__ float Xs[32][64];
    __shared__ float Ws[32][64];

    const int tid = threadIdx.x;
    const int rb = blockIdx.y * 64;
    const int cb = blockIdx.x * 64;
    const int ty = tid >> 5;
    const int tx = tid & 31;

    float2 acc[4][2];
    #pragma unroll
    for (int i = 0; i < 4; i++) { acc[i][0] = make_float2(0.f, 0.f); acc[i][1] = make_float2(0.f, 0.f); }

    const int lr = tid & 63;
    const int lk = (tid >> 6) * 8;

    for (int kc = 0; kc < DIMK; kc += 32) {
        __syncthreads();
        #pragma unroll
        for (int j = 0; j < 8; j += 4) {
            float4 xv = *(const float4*)(X + (size_t)(rb + lr) * DIMK + kc + lk + j);
            Xs[lk + j + 0][lr] = xv.x; Xs[lk + j + 1][lr] = xv.y;
            Xs[lk + j + 2][lr] = xv.z; Xs[lk + j + 3][lr] = xv.w;
            float4 wv = *(const float4*)(W + (size_t)(cb + lr) * DIMK + kc + lk + j);
            Ws[lk + j + 0][lr] = wv.x; Ws[lk + j + 1][lr] = wv.y;
            Ws[lk + j + 2][lr] = wv.z; Ws[lk + j + 3][lr] = wv.w;
        }
        __syncthreads();
        #pragma unroll
        for (int k = 0; k < 32; k++) {
            float4 a0 = *(const float4*)&Xs[k][ty * 8];
            float4 a1 = *(const float4*)&Xs[k][ty * 8 + 4];
            float2 wb = *(const float2*)&Ws[k][2 * tx];
            float2 ap0 = make_float2(a0.x, a0.y);
            float2 ap1 = make_float2(a0.z, a0.w);
            float2 ap2 = make_float2(a1.x, a1.y);
            float2 ap3 = make_float2(a1.z, a1.w);
            float2 bb0 = make_float2(wb.x, wb.x);
            float2 bb1 = make_float2(wb.y, wb.y);
            ffma2(acc[0][0], ap0, bb0); ffma2(acc[1][0], ap1, bb0);
            ffma2(acc[2][0], ap2, bb0); ffma2(acc[3][0], ap3, bb0);
            ffma2(acc[0][1], ap0, bb1); ffma2(acc[1][1], ap1, bb1);
            ffma2(acc[2][1], ap2, bb1); ffma2(acc[3][1], ap3, bb1);
        }
    }

    #pragma unroll
    for (int rp = 0; rp < 4; rp++) {
        #pragma unroll
        for (int cc = 0; cc < 2; cc++) {
            int col = cb + 2 * tx + cc;
            float bv = bias[col];
            int r0 = rb + ty * 8 + 2 * rp;
            out[(size_t)r0 * DIMK + col]       = (acc[rp][cc].x + bv) * sc;
            out[(size_t)(r0 + 1) * DIMK + col] = (acc[rp][cc].y + bv) * sc;
        }
    }
}

// ---------------------------------------------------------------------------
// Kernel B: 512 threads/block, 64-row stripe per block (grid=128).
// Column tiles of 256, BK=32 double-buffered. Micro-tile 8x4 per thread.
// 16 warps/SM (occupancy 25%) vs 8 before — the issue-latency fix.
// ---------------------------------------------------------------------------
#define CTILE     256
#define BK        32
#define STAGE_STRIDE 257                      // conflict-free row scans
#define AS_FLOATS    (DIMK * 64)              // 32768
#define BUF_FLOATS   (2 * BK * CTILE)         // 16384 (double buffer)
#define STAGE_FLOATS (64 * STAGE_STRIDE)      // 16448
#define UNION_FLOATS (STAGE_FLOATS)           // stage region ⊇ B buffers
#define SMEM_B_BYTES ((AS_FLOATS + UNION_FLOATS + 64 * KTOP) * 4 + 64 * KTOP * 4)

__global__ void __launch_bounds__(512, 1)
logits_topk_kernel(float* __restrict__ src_p, float* __restrict__ dst_p,
                   float* __restrict__ w_p)
{
    extern __shared__ float sm[];
    float* As   = sm;                                  // [512][64] k-major
    float* Bs   = sm + AS_FLOATS;                      // 2 x [32][256] k-major / stage
    float* topv = Bs + UNION_FLOATS;                   // [64][10]
    int*   topi = (int*)(topv + 64 * KTOP);            // [64][10]

    const int tid = threadIdx.x;
    const int rb  = blockIdx.x * 64;
    const int ty  = tid >> 6;        // 0..7 -> rows ty*8 .. ty*8+7
    const int tx  = tid & 63;        // cols 4*tx .. 4*tx+3

    for (int i = tid; i < 64 * KTOP; i += 512) {
        topv[i] = -INFINITY; topi[i] = 0;
    }

    // load A stripe: As[k][r], 64 rows x 512 k (per thread: 64 consecutive k)
    {
        const int lr = tid & 63;
        const int kb = (tid >> 6) * 64;
        const float* srcp = g_eh + (size_t)(rb + lr) * DIMK + kb;
        #pragma unroll 4
        for (int kk = 0; kk < 64; kk += 4) {
            float4 v = *(const float4*)(srcp + kk);
            As[(kb + kk + 0) * 64 + lr] = v.x;
            As[(kb + kk + 1) * 64 + lr] = v.y;
            As[(kb + kk + 2) * 64 + lr] = v.z;
            As[(kb + kk + 3) * 64 + lr] = v.w;
        }
    }
    __syncthreads();

    const int bc  = tid & 255;           // column within tile for B loads
    const int bkq = (tid >> 8) * 16;     // k-quarter (0 or 16) within chunk

    for (int ct = 0; ct < NROWS / CTILE; ct++) {
        const int cbase = ct * CTILE;
        const float* bsrc = g_et + (size_t)(cbase + bc) * DIMK + bkq;

        float2 acc[4][4];
        #pragma unroll
        for (int i = 0; i < 4; i++)
            #pragma unroll
            for (int j = 0; j < 4; j++) acc[i][j] = make_float2(0.f, 0.f);

        // prefetch + stage chunk 0 into buffer 0
        float4 pre[4];
        #pragma unroll
        for (int j = 0; j < 4; j++) pre[j] = *(const float4*)(bsrc + 4 * j);
        #pragma unroll
        for (int j = 0; j < 4; j++) {
            int kl = bkq + 4 * j;
            Bs[(kl + 0) * CTILE + bc] = pre[j].x;
            Bs[(kl + 1) * CTILE + bc] = pre[j].y;
            Bs[(kl + 2) * CTILE + bc] = pre[j].z;
            Bs[(kl + 3) * CTILE + bc] = pre[j].w;
        }

        for (int kc = 0; kc < DIMK / BK; kc++) {       // 16 chunks
            __syncthreads();
            if (kc < DIMK / BK - 1) {
                const float* ns = bsrc + (kc + 1) * BK;
                #pragma unroll
                for (int j = 0; j < 4; j++) pre[j] = *(const float4*)(ns + 4 * j);
            }
            const float* Bcur = Bs + (kc & 1) * (BK * CTILE);
            const float* Acur = As + (kc * BK) * 64 + ty * 8;
            #pragma unroll 8
            for (int k = 0; k < BK; k++) {
                float4 a0 = *(const float4*)(Acur + k * 64);
                float4 a1 = *(const float4*)(Acur + k * 64 + 4);
                float4 b  = *(const float4*)(Bcur + k * CTILE + tx * 4);
                float2 ap0 = make_float2(a0.x, a0.y);
                float2 ap1 = make_float2(a0.z, a0.w);
                float2 ap2 = make_float2(a1.x, a1.y);
                float2 ap3 = make_float2(a1.z, a1.w);
                float2 bb;
                bb = make_float2(b.x, b.x);
                ffma2(acc[0][0], ap0, bb); ffma2(acc[1][0], ap1, bb);
                ffma2(acc[2][0], ap2, bb); ffma2(acc[3][0], ap3, bb);
                bb = make_float2(b.y, b.y);
                ffma2(acc[0][1], ap0, bb); ffma2(acc[1][1], ap1, bb);
                ffma2(acc[2][1], ap2, bb); ffma2(acc[3][1], ap3, bb);
                bb = make_float2(b.z, b.z);
                ffma2(acc[0][2], ap0, bb); ffma2(acc[1][2], ap1, bb);
                ffma2(acc[2][2], ap2, bb); ffma2(acc[3][2], ap3, bb);
                bb = make_float2(b.w, b.w);
                ffma2(acc[0][3], ap0, bb); ffma2(acc[1][3], ap1, bb);
                ffma2(acc[2][3], ap2, bb); ffma2(acc[3][3], ap3, bb);
            }
            if (kc < DIMK / BK - 1) {
                float* Bn = Bs + ((kc + 1) & 1) * (BK * CTILE);
                #pragma unroll
                for (int j = 0; j < 4; j++) {
                    int kl = bkq + 4 * j;
                    Bn[(kl + 0) * CTILE + bc] = pre[j].x;
                    Bn[(kl + 1) * CTILE + bc] = pre[j].y;
                    Bn[(kl + 2) * CTILE + bc] = pre[j].z;
                    Bn[(kl + 3) * CTILE + bc] = pre[j].w;
                }
            }
        }
        __syncthreads();   // all B-buffer reads done before staging reuse

        // stage 64x256 logits tile (stride 257 -> conflict-free row scans)
        {
            const int r0 = ty * 8;
            #pragma unroll
            for (int rp = 0; rp < 4; rp++) {
                #pragma unroll
                for (int cc = 0; cc < 4; cc++) {
                    Bs[(r0 + 2 * rp) * STAGE_STRIDE + tx * 4 + cc]     = acc[rp][cc].x;
                    Bs[(r0 + 2 * rp + 1) * STAGE_STRIDE + tx * 4 + cc] = acc[rp][cc].y;
                }
            }
        }
        __syncthreads();

        // one thread per row: insertion into sorted top-10 (strict > keeps
        // lower index on ties, matching lax.top_k)
        if (tid < 64) {
            const int r = tid;
            float* tv = topv + r * KTOP;
            int*   ti = topi + r * KTOP;
            const float* crow = Bs + r * STAGE_STRIDE;
            float kv = tv[KTOP - 1];
            for (int c = 0; c < CTILE; c++) {
                float v = crow[c];
                if (v > kv) {
                    int j = KTOP - 1;
                    while (j > 0 && v > tv[j - 1]) {
                        tv[j] = tv[j - 1]; ti[j] = ti[j - 1]; j--;
                    }
                    tv[j] = v; ti[j] = cbase + c;
                    kv = tv[KTOP - 1];
                }
            }
        }
        __syncthreads();
    }

    // softmax + edge emission
    if (tid < 64) {
        const int r = tid, gr = rb + tid;
        float* tv = topv + r * KTOP;
        int*   ti = topi + r * KTOP;
        float m = tv[0];
        float e[KTOP]; float s = 0.f;
        #pragma unroll
        for (int j = 0; j < KTOP; j++) { e[j] = expf(tv[j] - m); s += e[j]; }
        #pragma unroll
        for (int j = 0; j < KTOP; j++) {
            int o = gr * KTOP + j;
            if (src_p) src_p[o] = (float)gr;
            if (dst_p) dst_p[o] = (float)ti[j];
            if (w_p)   w_p[o]   = e[j] / s;
        }
    }
}

// ---------------------------------------------------------------------------
extern "C" void kernel_launch(void* const* d_in, const int* in_sizes, int n_in,
                              void* d_out, int out_size)
{
    const float* X  = (const float*)d_in[0];
    const float* Wh = (const float*)d_in[1];
    const float* bh = (const float*)d_in[2];
    const float* Wt = (const float*)d_in[3];
    const float* bt = (const float*)d_in[4];

    cudaFuncSetAttribute(logits_topk_kernel,
                         cudaFuncAttributeMaxDynamicSharedMemorySize, SMEM_B_BYTES);

    embed_kernel<<<dim3(DIMK / 64, NROWS / 64, 2), 256>>>(X, Wh, bh, Wt, bt);

    const int NK = NROWS * KTOP;   // 81920
    float* out = (float*)d_out;
    float *sp = nullptr, *dp = nullptr, *wp = nullptr;
    if (out_size >= 3 * NK)      { sp = out; dp = out + NK; wp = out + 2 * NK; }
    else if (out_size == 2 * NK) { sp = out; dp = out + NK; }
    else                         { wp = out; }

    logits_topk_kernel<<<NROWS / 64, 512, SMEM_B_BYTES>>>(sp, dp, wp);
}